// round 5
// baseline (speedup 1.0000x reference)
#include <cuda_runtime.h>
#include <cuda_bf16.h>
#include <math_constants.h>

// Problem constants
#define BATCH 16
#define SEQ   4096
#define EMB   2048
#define WIN   64

#define ROWS_PER_BLOCK 8
#define BLOCKS_PER_BATCH (SEQ / ROWS_PER_BLOCK)   // 512
#define NWIN (SEQ - WIN + 1)                      // 4033 window starts

// Scratch (static device arrays: allocation-free; zero-initialized at load)
__device__ float        g_scores[BATCH * SEQ];
__device__ unsigned int g_cnt[BATCH];   // per-batch completed-block counters

// ---------------------------------------------------------------------------
// Fused kernel:
//   Phase A (all 8192 blocks): one warp per row, s[b,t] = mask ? x.W + b : 0
//   Phase B (last-finishing block of each batch): sliding-window(64) mean max
// ---------------------------------------------------------------------------
__global__ __launch_bounds__(256) void fused_kernel(
    const float* __restrict__ x,
    const int*   __restrict__ mask,   // bool mask coerced to int32 by harness
    const float* __restrict__ W,
    const float* __restrict__ bias,
    float*       __restrict__ out)
{
    __shared__ float sW[EMB];                 // 8 KB
    __shared__ float s[SEQ];                  // 16 KB (phase B stage)
    __shared__ float red[ROWS_PER_BLOCK];
    __shared__ unsigned int sFin;

    const int tid  = threadIdx.x;
    const int wid  = tid >> 5;
    const int lane = tid & 31;
    const int b    = blockIdx.x / BLOCKS_PER_BATCH;     // batch of this block
    const int row  = blockIdx.x * ROWS_PER_BLOCK + wid; // global row (b*SEQ+t)

    for (int i = tid; i < EMB; i += 256)
        sW[i] = W[i];
    __syncthreads();

    // ---------------- Phase A: score this block's 8 rows -------------------
    int m = (lane == 0) ? mask[row] : 0;   // prefetch mask early

    const float4* __restrict__ xr = reinterpret_cast<const float4*>(x + (size_t)row * EMB);
    const float4* __restrict__ wr = reinterpret_cast<const float4*>(sW);

    float acc = 0.0f;
    // 512 float4/row, 32 lanes -> 16/lane; two half-passes of 8 batched loads
    #pragma unroll
    for (int h = 0; h < 2; h++) {
        float4 a[8];
        #pragma unroll
        for (int j = 0; j < 8; j++)
            a[j] = __ldcs(&xr[lane + (h * 8 + j) * 32]);
        #pragma unroll
        for (int j = 0; j < 8; j++) {
            float4 w = wr[lane + (h * 8 + j) * 32];
            acc = fmaf(a[j].x, w.x, acc);
            acc = fmaf(a[j].y, w.y, acc);
            acc = fmaf(a[j].z, w.z, acc);
            acc = fmaf(a[j].w, w.w, acc);
        }
    }

    #pragma unroll
    for (int o = 16; o > 0; o >>= 1)
        acc += __shfl_xor_sync(0xffffffffu, acc, o);

    if (lane == 0) {
        g_scores[row] = (m != 0) ? (acc + bias[0]) : 0.0f;
        __threadfence();   // make this warp's score globally visible
    }
    __syncthreads();       // all 8 writers have fenced

    // ---------------- Completion protocol ----------------------------------
    if (tid == 0) {
        unsigned int r = atomicAdd(&g_cnt[b], 1u);
        sFin = (r == BLOCKS_PER_BATCH - 1) ? 1u : 0u;
        if (sFin) __threadfence();   // acquire: order counter read before score reads
    }
    __syncthreads();
    if (!sFin) return;

    // ---------------- Phase B: finisher for batch b -------------------------
    // Stage all 4096 scores of this batch (L2-hot) into shared
    {
        const float4* src = reinterpret_cast<const float4*>(g_scores + b * SEQ);
        float4*       dst = reinterpret_cast<float4*>(s);
        #pragma unroll
        for (int i = 0; i < SEQ / 4 / 256; i++)   // 4 iters
            dst[tid + i * 256] = src[tid + i * 256];
    }
    __syncthreads();

    // Thread t covers window starts 16t .. 16t+15 via rolling sum
    const int start0 = tid * 16;
    float best = -CUDART_INF_F;
    if (start0 < NWIN) {
        const float4* sv = reinterpret_cast<const float4*>(s) + tid * 4;
        float sum = 0.0f;
        #pragma unroll
        for (int k = 0; k < WIN / 4; k++) {
            float4 v = sv[k];
            sum += (v.x + v.y) + (v.z + v.w);
        }
        best = sum;
        #pragma unroll
        for (int j = 1; j < 16; j++) {
            int i = start0 + j;
            if (i < NWIN) {
                sum += s[i + WIN - 1] - s[i - 1];
                best = fmaxf(best, sum);
            }
        }
    }

    // Block max reduce (8 warps)
    #pragma unroll
    for (int o = 16; o > 0; o >>= 1)
        best = fmaxf(best, __shfl_xor_sync(0xffffffffu, best, o));
    if (lane == 0) red[wid] = best;
    __syncthreads();

    if (tid == 0) {
        float v = red[0];
        #pragma unroll
        for (int i = 1; i < ROWS_PER_BLOCK; i++)
            v = fmaxf(v, red[i]);
        out[b] = v * (1.0f / (float)WIN);
        g_cnt[b] = 0u;     // reset for next graph replay
    }
}

// ---------------------------------------------------------------------------
// Launch: single fused kernel
// ---------------------------------------------------------------------------
extern "C" void kernel_launch(void* const* d_in, const int* in_sizes, int n_in,
                              void* d_out, int out_size)
{
    const float* x    = (const float*)d_in[0];
    const int*   mask = (const int*)d_in[1];
    const float* W    = (const float*)d_in[2];
    const float* bias = (const float*)d_in[3];
    float*       out  = (float*)d_out;

    fused_kernel<<<BATCH * BLOCKS_PER_BATCH, 256>>>(x, mask, W, bias, out);
}

// round 6
// speedup vs baseline: 1.0804x; 1.0804x over previous
#include <cuda_runtime.h>
#include <cuda_bf16.h>
#include <math_constants.h>

// Problem constants
#define BATCH 16
#define SEQ   4096
#define EMB   2048
#define WIN   64

// Scratch for per-token scores (static device array: allocation-free)
__device__ float g_scores[BATCH * SEQ];

// ---------------------------------------------------------------------------
// Kernel 1: s[b,t] = mask[b,t] ? dot(x[b,t,:], W) + bias : 0
// One warp per row. Streaming float4 loads (MLP=8), W in shared.
// ---------------------------------------------------------------------------
__global__ __launch_bounds__(256) void score_kernel(
    const float* __restrict__ x,
    const int*   __restrict__ mask,   // bool mask coerced to int32 by harness
    const float* __restrict__ W,
    const float* __restrict__ bias)
{
    __shared__ float sW[EMB];
    for (int i = threadIdx.x; i < EMB; i += blockDim.x)
        sW[i] = W[i];
    __syncthreads();

    const int warpsPerBlock = blockDim.x >> 5;
    const int warp = blockIdx.x * warpsPerBlock + (threadIdx.x >> 5);
    const int lane = threadIdx.x & 31;
    if (warp >= BATCH * SEQ) return;

    // Prefetch mask early (lane 0 only needs it)
    int m = (lane == 0) ? mask[warp] : 0;

    const float4* __restrict__ xr = reinterpret_cast<const float4*>(x + (size_t)warp * EMB);
    const float4* __restrict__ wr = reinterpret_cast<const float4*>(sW);

    float acc = 0.0f;
    // 512 float4/row, 32 lanes -> 16/lane; two half-passes of 8 batched
    // streaming LDG.128 (MLP=8).
    #pragma unroll
    for (int h = 0; h < 2; h++) {
        float4 a[8];
        #pragma unroll
        for (int j = 0; j < 8; j++)
            a[j] = __ldcs(&xr[lane + (h * 8 + j) * 32]);
        #pragma unroll
        for (int j = 0; j < 8; j++) {
            float4 w = wr[lane + (h * 8 + j) * 32];
            acc = fmaf(a[j].x, w.x, acc);
            acc = fmaf(a[j].y, w.y, acc);
            acc = fmaf(a[j].z, w.z, acc);
            acc = fmaf(a[j].w, w.w, acc);
        }
    }

    // warp reduce
    #pragma unroll
    for (int o = 16; o > 0; o >>= 1)
        acc += __shfl_xor_sync(0xffffffffu, acc, o);

    if (lane == 0) {
        g_scores[warp] = (m != 0) ? (acc + bias[0]) : 0.0f;
    }
}

// ---------------------------------------------------------------------------
// Kernel 2: per batch, sliding-window(64) sums over S=4096 scores, take max,
// divide by WIN at the end. One block (1024 threads) per batch.
// Launched with PDL: blocks spin up during kernel 1's tail; the grid-dependency
// sync gates the g_scores reads.
// ---------------------------------------------------------------------------
__global__ __launch_bounds__(1024) void window_max_kernel(float* __restrict__ out)
{
    __shared__ float s[SEQ];
    __shared__ float red[32];

    const int b   = blockIdx.x;
    const int tid = threadIdx.x;

    // Pre-dependency work: nothing but address math; ramp overlap is the win.
    const float4* src = reinterpret_cast<const float4*>(g_scores + b * SEQ);
    float4*       dst = reinterpret_cast<float4*>(s);

    // Wait for score_kernel completion (PDL dependency)
    cudaGridDependencySynchronize();

    if (tid < SEQ / 4) dst[tid] = src[tid];
    __syncthreads();

    // windows 0 .. SEQ-WIN (4033 windows). Thread t covers starts 4t..4t+3.
    const int start = tid * 4;
    float best = -CUDART_INF_F;
    if (start <= SEQ - WIN) {
        float sum = 0.0f;
        #pragma unroll
        for (int k = 0; k < WIN; k++)
            sum += s[start + k];
        best = sum;
        #pragma unroll
        for (int j = 1; j < 4; j++) {
            int i = start + j;
            if (i <= SEQ - WIN) {
                sum += s[i + WIN - 1] - s[i - 1];
                best = fmaxf(best, sum);
            }
        }
    }

    // block max reduce: warp shuffle, then cross-warp via smem
    #pragma unroll
    for (int o = 16; o > 0; o >>= 1)
        best = fmaxf(best, __shfl_xor_sync(0xffffffffu, best, o));
    if ((tid & 31) == 0) red[tid >> 5] = best;
    __syncthreads();
    if (tid < 32) {
        float v = red[tid];  // blockDim=1024 -> exactly 32 warps
        #pragma unroll
        for (int o = 16; o > 0; o >>= 1)
            v = fmaxf(v, __shfl_xor_sync(0xffffffffu, v, o));
        if (tid == 0)
            out[b] = v * (1.0f / (float)WIN);
    }
}

// ---------------------------------------------------------------------------
// Launch: kernel 1 normally, kernel 2 via PDL (programmatic stream serialization)
// ---------------------------------------------------------------------------
extern "C" void kernel_launch(void* const* d_in, const int* in_sizes, int n_in,
                              void* d_out, int out_size)
{
    const float* x    = (const float*)d_in[0];
    const int*   mask = (const int*)d_in[1];
    const float* W    = (const float*)d_in[2];
    const float* bias = (const float*)d_in[3];
    float*       out  = (float*)d_out;

    // Kernel 1: one warp per row, 8 warps per 256-thread block
    const int totalRows = BATCH * SEQ;               // 65536
    const int warpsPerBlock = 256 / 32;              // 8
    const int grid1 = (totalRows + warpsPerBlock - 1) / warpsPerBlock; // 8192
    score_kernel<<<grid1, 256>>>(x, mask, W, bias);

    // Kernel 2 with programmatic dependent launch
    cudaLaunchConfig_t cfg = {};
    cfg.gridDim  = dim3(BATCH, 1, 1);
    cfg.blockDim = dim3(1024, 1, 1);
    cfg.dynamicSmemBytes = 0;
    cfg.stream = 0;
    cudaLaunchAttribute attrs[1];
    attrs[0].id = cudaLaunchAttributeProgrammaticStreamSerialization;
    attrs[0].val.programmaticStreamSerializationAllowed = 1;
    cfg.attrs = attrs;
    cfg.numAttrs = 1;
    cudaLaunchKernelEx(&cfg, window_max_kernel, out);
}

// round 7
// speedup vs baseline: 1.1679x; 1.0810x over previous
#include <cuda_runtime.h>
#include <cuda_bf16.h>
#include <math_constants.h>

// Problem constants
#define BATCH 16
#define SEQ   4096
#define EMB   2048
#define WIN   64

// Scratch for per-token scores (static device array: allocation-free)
__device__ float g_scores[BATCH * SEQ];

// ---------------------------------------------------------------------------
// Kernel 1: s[b,t] = mask[b,t] ? dot(x[b,t,:], W) + bias : 0
// One warp per row. Masked rows SKIP the x read entirely (~10% HBM savings).
// Streaming float4 loads (MLP=8), W in shared.
// ---------------------------------------------------------------------------
__global__ __launch_bounds__(256) void score_kernel(
    const float* __restrict__ x,
    const int*   __restrict__ mask,   // bool mask coerced to int32 by harness
    const float* __restrict__ W,
    const float* __restrict__ bias)
{
    __shared__ float sW[EMB];
    for (int i = threadIdx.x; i < EMB; i += blockDim.x)
        sW[i] = W[i];
    __syncthreads();

    const int warpsPerBlock = blockDim.x >> 5;
    const int warp = blockIdx.x * warpsPerBlock + (threadIdx.x >> 5);
    const int lane = threadIdx.x & 31;
    if (warp >= BATCH * SEQ) return;

    // Mask gate: skip the entire 8KB row read when masked out.
    // All lanes hit the same address -> single broadcast wavefront.
    const int m = mask[warp];
    if (m == 0) {
        if (lane == 0) g_scores[warp] = 0.0f;
        return;
    }

    const float4* __restrict__ xr = reinterpret_cast<const float4*>(x + (size_t)warp * EMB);
    const float4* __restrict__ wr = reinterpret_cast<const float4*>(sW);

    float acc = 0.0f;
    // 512 float4/row, 32 lanes -> 16/lane; two half-passes of 8 batched
    // streaming LDG.128 (MLP=8).
    #pragma unroll
    for (int h = 0; h < 2; h++) {
        float4 a[8];
        #pragma unroll
        for (int j = 0; j < 8; j++)
            a[j] = __ldcs(&xr[lane + (h * 8 + j) * 32]);
        #pragma unroll
        for (int j = 0; j < 8; j++) {
            float4 w = wr[lane + (h * 8 + j) * 32];
            acc = fmaf(a[j].x, w.x, acc);
            acc = fmaf(a[j].y, w.y, acc);
            acc = fmaf(a[j].z, w.z, acc);
            acc = fmaf(a[j].w, w.w, acc);
        }
    }

    // warp reduce
    #pragma unroll
    for (int o = 16; o > 0; o >>= 1)
        acc += __shfl_xor_sync(0xffffffffu, acc, o);

    if (lane == 0)
        g_scores[warp] = acc + bias[0];
}

// ---------------------------------------------------------------------------
// Kernel 2: per batch, sliding-window(64) sums over S=4096 scores, take max,
// divide by WIN at the end. One block (1024 threads) per batch. PDL-launched.
// ---------------------------------------------------------------------------
__global__ __launch_bounds__(1024) void window_max_kernel(float* __restrict__ out)
{
    __shared__ float s[SEQ];
    __shared__ float red[32];

    const int b   = blockIdx.x;
    const int tid = threadIdx.x;

    const float4* src = reinterpret_cast<const float4*>(g_scores + b * SEQ);
    float4*       dst = reinterpret_cast<float4*>(s);

    // Wait for score_kernel completion (PDL dependency)
    cudaGridDependencySynchronize();

    if (tid < SEQ / 4) dst[tid] = src[tid];
    __syncthreads();

    // windows 0 .. SEQ-WIN (4033 windows). Thread t covers starts 4t..4t+3.
    const int start = tid * 4;
    float best = -CUDART_INF_F;
    if (start <= SEQ - WIN) {
        float sum = 0.0f;
        #pragma unroll
        for (int k = 0; k < WIN; k++)
            sum += s[start + k];
        best = sum;
        #pragma unroll
        for (int j = 1; j < 4; j++) {
            int i = start + j;
            if (i <= SEQ - WIN) {
                sum += s[i + WIN - 1] - s[i - 1];
                best = fmaxf(best, sum);
            }
        }
    }

    // block max reduce: warp shuffle, then cross-warp via smem
    #pragma unroll
    for (int o = 16; o > 0; o >>= 1)
        best = fmaxf(best, __shfl_xor_sync(0xffffffffu, best, o));
    if ((tid & 31) == 0) red[tid >> 5] = best;
    __syncthreads();
    if (tid < 32) {
        float v = red[tid];  // blockDim=1024 -> exactly 32 warps
        #pragma unroll
        for (int o = 16; o > 0; o >>= 1)
            v = fmaxf(v, __shfl_xor_sync(0xffffffffu, v, o));
        if (tid == 0)
            out[b] = v * (1.0f / (float)WIN);
    }
}

// ---------------------------------------------------------------------------
// Launch: kernel 1 normally, kernel 2 via PDL (programmatic stream serialization)
// ---------------------------------------------------------------------------
extern "C" void kernel_launch(void* const* d_in, const int* in_sizes, int n_in,
                              void* d_out, int out_size)
{
    const float* x    = (const float*)d_in[0];
    const int*   mask = (const int*)d_in[1];
    const float* W    = (const float*)d_in[2];
    const float* bias = (const float*)d_in[3];
    float*       out  = (float*)d_out;

    // Kernel 1: one warp per row, 8 warps per 256-thread block
    const int totalRows = BATCH * SEQ;               // 65536
    const int warpsPerBlock = 256 / 32;              // 8
    const int grid1 = (totalRows + warpsPerBlock - 1) / warpsPerBlock; // 8192
    score_kernel<<<grid1, 256>>>(x, mask, W, bias);

    // Kernel 2 with programmatic dependent launch
    cudaLaunchConfig_t cfg = {};
    cfg.gridDim  = dim3(BATCH, 1, 1);
    cfg.blockDim = dim3(1024, 1, 1);
    cfg.dynamicSmemBytes = 0;
    cfg.stream = 0;
    cudaLaunchAttribute attrs[1];
    attrs[0].id = cudaLaunchAttributeProgrammaticStreamSerialization;
    attrs[0].val.programmaticStreamSerializationAllowed = 1;
    cfg.attrs = attrs;
    cfg.numAttrs = 1;
    cudaLaunchKernelEx(&cfg, window_max_kernel, out);
}